// round 1
// baseline (speedup 1.0000x reference)
#include <cuda_runtime.h>
#include <cuda_bf16.h>

// Problem constants
// B=8, CIN=256, COUT=512, DK=256, DV=256, NH=8, H=W=32, DKH=DVH=32
#define HW 1024

// Scratch (static device globals: allocation-free rule)
__device__ float g_wT[2304 * 1024];      // combined conv weights, K-major: [(ci*9+k)][co] co: 0..255 conv, 256..1023 qkv
__device__ float g_watT[256 * 256];      // w_att transposed: [ci][co]
__device__ float g_qkv[8 * 768 * 1024];  // qkv conv output (b, 768, HW)
__device__ float g_att[8 * 256 * 1024];  // attention output, already in (b, C, H, W) layout for 1x1 conv

// ---------------------------------------------------------------------------
// Kernel 0: weight preparation (transpose to K-major)
// ---------------------------------------------------------------------------
__global__ void prep_weights(const float* __restrict__ wc,
                             const float* __restrict__ wq,
                             const float* __restrict__ wa) {
    int idx = blockIdx.x * 256 + threadIdx.x;
    if (idx < 2304 * 1024) {
        int co = idx & 1023;
        int rk = idx >> 10;          // ci*9 + k
        int ci = rk / 9;
        int k  = rk - ci * 9;
        float v = (co < 256) ? wc[(co * 256 + ci) * 9 + k]
                             : wq[((co - 256) * 256 + ci) * 9 + k];
        g_wT[idx] = v;
    }
    if (idx < 256 * 256) {
        int co = idx & 255;
        int ci = idx >> 8;
        g_watT[idx] = wa[co * 256 + ci];
    }
}

// ---------------------------------------------------------------------------
// Kernel 1: fused 3x3 conv (1024 output channels = 256 xo + 768 qkv)
// Block: 256 threads, tile = 64 co x 64 pixels (8x8 spatial), 4x4 per thread.
// ---------------------------------------------------------------------------
__global__ __launch_bounds__(256) void conv3x3_kernel(
    const float* __restrict__ x,
    const float* __restrict__ bconv,
    const float* __restrict__ bqkv,
    float* __restrict__ out) {
    __shared__ float Ws[72 * 64];      // [cil*9+k][64 co]
    __shared__ float Xs[8 * 10 * 12];  // [cil][10 rows][12 pitch]

    const int t  = threadIdx.x;
    const int tx = t & 15;       // co group
    const int ty = t >> 4;       // pixel group
    const int b      = blockIdx.z;
    const int coBase = blockIdx.x * 64;
    const int pt     = blockIdx.y;
    const int py0 = (pt >> 2) * 8;
    const int px0 = (pt & 3) * 8;
    const int r   = ty >> 1;           // row within 8x8 tile
    const int ccB = (ty & 1) * 4;      // col base within 8x8 tile

    float acc[4][4];
#pragma unroll
    for (int i = 0; i < 4; ++i)
#pragma unroll
        for (int j = 0; j < 4; ++j) acc[i][j] = 0.f;

    for (int ciBase = 0; ciBase < 256; ciBase += 8) {
        __syncthreads();
        // Load input patch with halo (8 ci x 10 x 10), zero-padded
#pragma unroll
        for (int i = 0; i < 4; ++i) {
            int idx = t + i * 256;
            if (idx < 800) {
                int cil = idx / 100;
                int rem = idx - cil * 100;
                int ly = rem / 10;
                int lx = rem - ly * 10;
                int gy = py0 + ly - 1;
                int gx = px0 + lx - 1;
                float v = 0.f;
                if ((unsigned)gy < 32u && (unsigned)gx < 32u)
                    v = x[((b * 256 + ciBase + cil) * 32 + gy) * 32 + gx];
                Xs[cil * 120 + ly * 12 + lx] = v;
            }
        }
        // Load weights (coalesced from K-major transposed buffer)
        {
            const float* src = &g_wT[(ciBase * 9) * 1024 + coBase];
#pragma unroll
            for (int i = 0; i < 18; ++i) {
                int idx = t + i * 256;       // 0..4607
                int col = idx & 63;
                int rk  = idx >> 6;          // 0..71
                Ws[idx] = src[rk * 1024 + col];
            }
        }
        __syncthreads();

#pragma unroll 1
        for (int cil = 0; cil < 8; ++cil) {
#pragma unroll
            for (int ky = 0; ky < 3; ++ky) {
                const float* xp = &Xs[cil * 120 + (r + ky) * 12 + ccB];
                float4 xa = *(const float4*)xp;
                float4 xb = *(const float4*)(xp + 4);
                float xv[8] = {xa.x, xa.y, xa.z, xa.w, xb.x, xb.y, xb.z, xb.w};
#pragma unroll
                for (int kx = 0; kx < 3; ++kx) {
                    float4 wv = *(const float4*)&Ws[(cil * 9 + ky * 3 + kx) * 64 + tx * 4];
                    float wr[4] = {wv.x, wv.y, wv.z, wv.w};
#pragma unroll
                    for (int i = 0; i < 4; ++i)
#pragma unroll
                        for (int j = 0; j < 4; ++j)
                            acc[i][j] += wr[i] * xv[kx + j];
                }
            }
        }
    }

    // Epilogue: co<256 -> xo half of d_out; co>=256 -> qkv scratch
#pragma unroll
    for (int i = 0; i < 4; ++i) {
        int co = coBase + tx * 4 + i;
#pragma unroll
        for (int j = 0; j < 4; ++j) {
            int p = (py0 + r) * 32 + px0 + ccB + j;
            float v = acc[i][j];
            if (co < 256) {
                out[(b * 512 + co) * 1024 + p] = v + bconv[co];
            } else {
                g_qkv[(b * 768 + co - 256) * 1024 + p] = v + bqkv[co - 256];
            }
        }
    }
}

// ---------------------------------------------------------------------------
// Kernel 2: flash attention per (b, h). One warp per query row (8 rows/block).
// Key/value tiles of 128 staged in smem; lane owns 4 keys; O partials in regs.
// Output written in the reference's reshape layout: channel = h*32 + m/32,
// y = m%32, x = d.
// ---------------------------------------------------------------------------
__global__ __launch_bounds__(256) void attention_kernel(
    const float* __restrict__ krw,   // key_rel_w (63, 32)
    const float* __restrict__ krh) { // key_rel_h (63, 32)
    __shared__ float kt[32 * 128];
    __shared__ float vt[32 * 128];
    __shared__ float relw[8][64];
    __shared__ float relh[8][64];

    const int t = threadIdx.x;
    const int lane = t & 31;
    const int w = t >> 5;
    const int b = blockIdx.z;
    const int h = blockIdx.y;
    const int m = blockIdx.x * 8 + w;   // query index in [0, 1024)
    const int qx = m >> 5;              // H index
    const int qy = m & 31;              // W index

    // Load scaled q row into registers (broadcast across lanes)
    const float* qbase = &g_qkv[(b * 768 + h * 32) * 1024 + m];
    float q[32];
#pragma unroll
    for (int d = 0; d < 32; ++d) q[d] = qbase[d * 1024] * 0.17677669529663687f;

    // Precompute rel dot products: rwq[mm] = q . key_rel_w[mm], similarly rhq
    for (int mm = lane; mm < 63; mm += 32) {
        float sw = 0.f, sh = 0.f;
#pragma unroll
        for (int d = 0; d < 32; ++d) {
            sw += q[d] * krw[mm * 32 + d];
            sh += q[d] * krh[mm * 32 + d];
        }
        relw[w][mm] = sw;
        relh[w][mm] = sh;
    }
    __syncwarp();

    float o[32];
#pragma unroll
    for (int d = 0; d < 32; ++d) o[d] = 0.f;
    float M = -1e30f, L = 0.f;

    const float* kg = &g_qkv[(b * 768 + 256 + h * 32) * 1024];
    const float* vg = &g_qkv[(b * 768 + 512 + h * 32) * 1024];

    for (int tile = 0; tile < 8; ++tile) {
        __syncthreads();
#pragma unroll
        for (int i = 0; i < 16; ++i) {
            int idx = t + i * 256;           // 0..4095
            int d  = idx >> 7;
            int nl = idx & 127;
            kt[idx] = kg[d * 1024 + tile * 128 + nl];
            vt[idx] = vg[d * 1024 + tile * 128 + nl];
        }
        __syncthreads();

        // S phase: 4 keys per lane
        float s0 = 0.f, s1 = 0.f, s2 = 0.f, s3 = 0.f;
#pragma unroll
        for (int d = 0; d < 32; ++d) {
            float4 kv = *(const float4*)&kt[d * 128 + lane * 4];
            s0 += q[d] * kv.x; s1 += q[d] * kv.y;
            s2 += q[d] * kv.z; s3 += q[d] * kv.w;
        }
        // relative position terms: key n = tile*128 + lane*4 + j
        {
            int n0 = tile * 128 + lane * 4;
            int i0 = n0 >> 5;         // key row (all 4 keys share it: lane*4+3 < next multiple of 32)
            int j0 = n0 & 31;         // key col base
            float rh = relh[w][i0 - qx + 31];
            s0 += relw[w][j0     - qy + 31] + rh;
            s1 += relw[w][j0 + 1 - qy + 31] + rh;
            s2 += relw[w][j0 + 2 - qy + 31] + rh;
            s3 += relw[w][j0 + 3 - qy + 31] + rh;
        }
        // Online softmax update
        float mx = fmaxf(fmaxf(s0, s1), fmaxf(s2, s3));
#pragma unroll
        for (int off = 16; off; off >>= 1)
            mx = fmaxf(mx, __shfl_xor_sync(0xffffffffu, mx, off));
        float newM = fmaxf(M, mx);
        float scale = __expf(M - newM);
        M = newM;
        float e0 = __expf(s0 - newM), e1 = __expf(s1 - newM);
        float e2 = __expf(s2 - newM), e3 = __expf(s3 - newM);
        L = L * scale + (e0 + e1) + (e2 + e3);
        // O phase
#pragma unroll
        for (int d = 0; d < 32; ++d) {
            float4 vv = *(const float4*)&vt[d * 128 + lane * 4];
            o[d] = o[d] * scale + e0 * vv.x + e1 * vv.y + e2 * vv.z + e3 * vv.w;
        }
    }

    // Cross-lane reductions
#pragma unroll
    for (int off = 16; off; off >>= 1)
        L += __shfl_xor_sync(0xffffffffu, L, off);
    float of = 0.f;
#pragma unroll
    for (int d = 0; d < 32; ++d) {
        float v = o[d];
#pragma unroll
        for (int off = 16; off; off >>= 1)
            v += __shfl_xor_sync(0xffffffffu, v, off);
        if (lane == d) of = v;
    }
    // att.reshape(b, DV, H, W): channel = h*32 + qx, y = qy, x = d(=lane)
    g_att[((b * 256 + h * 32 + qx) * 32 + qy) * 32 + lane] = of / L;
}

// ---------------------------------------------------------------------------
// Kernel 3: 1x1 conv (GEMM M=256, N=1024, K=256 per batch) -> out[:, 256:512]
// ---------------------------------------------------------------------------
__global__ __launch_bounds__(256) void conv1x1_kernel(
    const float* __restrict__ batt,
    float* __restrict__ out) {
    __shared__ float Wk[16 * 64];
    __shared__ float Ak[16 * 64];
    const int t  = threadIdx.x;
    const int tx = t & 15;
    const int ty = t >> 4;
    const int b      = blockIdx.z;
    const int coBase = blockIdx.x * 64;
    const int pBase  = blockIdx.y * 64;

    float acc[4][4];
#pragma unroll
    for (int i = 0; i < 4; ++i)
#pragma unroll
        for (int j = 0; j < 4; ++j) acc[i][j] = 0.f;

    for (int ciB = 0; ciB < 256; ciB += 16) {
        __syncthreads();
#pragma unroll
        for (int i = 0; i < 4; ++i) {
            int idx = t + i * 256;
            int col = idx & 63;
            int cil = idx >> 6;
            Wk[idx] = g_watT[(ciB + cil) * 256 + coBase + col];
            Ak[idx] = g_att[(b * 256 + ciB + cil) * 1024 + pBase + col];
        }
        __syncthreads();
#pragma unroll
        for (int cil = 0; cil < 16; ++cil) {
            float4 wv = *(const float4*)&Wk[cil * 64 + tx * 4];
            float4 av = *(const float4*)&Ak[cil * 64 + ty * 4];
            float wr[4] = {wv.x, wv.y, wv.z, wv.w};
            float ar[4] = {av.x, av.y, av.z, av.w};
#pragma unroll
            for (int i = 0; i < 4; ++i)
#pragma unroll
                for (int j = 0; j < 4; ++j)
                    acc[i][j] += wr[i] * ar[j];
        }
    }

#pragma unroll
    for (int i = 0; i < 4; ++i) {
        int co = coBase + tx * 4 + i;
        float bb = batt[co];
#pragma unroll
        for (int j = 0; j < 4; ++j) {
            int p = pBase + ty * 4 + j;
            out[(b * 512 + 256 + co) * 1024 + p] = acc[i][j] + bb;
        }
    }
}

// ---------------------------------------------------------------------------
// Launch
// ---------------------------------------------------------------------------
extern "C" void kernel_launch(void* const* d_in, const int* in_sizes, int n_in,
                              void* d_out, int out_size) {
    const float* x      = (const float*)d_in[0];
    const float* w_conv = (const float*)d_in[1];
    const float* b_conv = (const float*)d_in[2];
    const float* w_qkv  = (const float*)d_in[3];
    const float* b_qkv  = (const float*)d_in[4];
    const float* w_att  = (const float*)d_in[5];
    const float* b_att  = (const float*)d_in[6];
    const float* krw    = (const float*)d_in[7];
    const float* krh    = (const float*)d_in[8];
    float* out = (float*)d_out;

    prep_weights<<<(2304 * 1024 + 255) / 256, 256>>>(w_conv, w_qkv, w_att);
    conv3x3_kernel<<<dim3(16, 16, 8), 256>>>(x, b_conv, b_qkv, out);
    attention_kernel<<<dim3(128, 8, 8), 256>>>(krw, krh);
    conv1x1_kernel<<<dim3(4, 16, 8), 256>>>(b_att, out);
}

// round 2
// speedup vs baseline: 1.0013x; 1.0013x over previous
#include <cuda_runtime.h>
#include <cuda_bf16.h>

// Problem constants
// B=8, CIN=256, COUT=512, DK=256, DV=256, NH=8, H=W=32, DKH=DVH=32
#define HW 1024

// Scratch (static device globals: allocation-free rule)
__device__ float g_wT[2304 * 1024];      // combined conv weights, K-major: [(ci*9+k)][co] co: 0..255 conv, 256..1023 qkv
__device__ float g_watT[256 * 256];      // w_att transposed: [ci][co]
__device__ float g_qkv[8 * 768 * 1024];  // qkv conv output (b, 768, HW)
__device__ float g_att[8 * 256 * 1024];  // attention output, already in (b, C, H, W) layout for 1x1 conv

// ---------------------------------------------------------------------------
// Kernel 0: weight preparation (transpose to K-major)
// ---------------------------------------------------------------------------
__global__ void prep_weights(const float* __restrict__ wc,
                             const float* __restrict__ wq,
                             const float* __restrict__ wa) {
    int idx = blockIdx.x * 256 + threadIdx.x;
    if (idx < 2304 * 1024) {
        int co = idx & 1023;
        int rk = idx >> 10;          // ci*9 + k
        int ci = rk / 9;
        int k  = rk - ci * 9;
        float v = (co < 256) ? wc[(co * 256 + ci) * 9 + k]
                             : wq[((co - 256) * 256 + ci) * 9 + k];
        g_wT[idx] = v;
    }
    if (idx < 256 * 256) {
        int co = idx & 255;
        int ci = idx >> 8;
        g_watT[idx] = wa[co * 256 + ci];
    }
}

// ---------------------------------------------------------------------------
// Kernel 1: fused 3x3 conv (1024 output channels = 256 xo + 768 qkv)
// Block: 256 threads, tile = 64 co x 64 pixels (8x8 spatial), 4x4 per thread.
// ---------------------------------------------------------------------------
__global__ __launch_bounds__(256) void conv3x3_kernel(
    const float* __restrict__ x,
    const float* __restrict__ bconv,
    const float* __restrict__ bqkv,
    float* __restrict__ out) {
    __shared__ float Ws[72 * 64];      // [cil*9+k][64 co]
    __shared__ float Xs[8 * 10 * 12];  // [cil][10 rows][12 pitch]

    const int t  = threadIdx.x;
    const int tx = t & 15;       // co group
    const int ty = t >> 4;       // pixel group
    const int b      = blockIdx.z;
    const int coBase = blockIdx.x * 64;
    const int pt     = blockIdx.y;
    const int py0 = (pt >> 2) * 8;
    const int px0 = (pt & 3) * 8;
    const int r   = ty >> 1;           // row within 8x8 tile
    const int ccB = (ty & 1) * 4;      // col base within 8x8 tile

    float acc[4][4];
#pragma unroll
    for (int i = 0; i < 4; ++i)
#pragma unroll
        for (int j = 0; j < 4; ++j) acc[i][j] = 0.f;

    for (int ciBase = 0; ciBase < 256; ciBase += 8) {
        __syncthreads();
        // Load input patch with halo (8 ci x 10 x 10), zero-padded
#pragma unroll
        for (int i = 0; i < 4; ++i) {
            int idx = t + i * 256;
            if (idx < 800) {
                int cil = idx / 100;
                int rem = idx - cil * 100;
                int ly = rem / 10;
                int lx = rem - ly * 10;
                int gy = py0 + ly - 1;
                int gx = px0 + lx - 1;
                float v = 0.f;
                if ((unsigned)gy < 32u && (unsigned)gx < 32u)
                    v = x[((b * 256 + ciBase + cil) * 32 + gy) * 32 + gx];
                Xs[cil * 120 + ly * 12 + lx] = v;
            }
        }
        // Load weights (coalesced from K-major transposed buffer)
        {
            const float* src = &g_wT[(ciBase * 9) * 1024 + coBase];
#pragma unroll
            for (int i = 0; i < 18; ++i) {
                int idx = t + i * 256;       // 0..4607
                int col = idx & 63;
                int rk  = idx >> 6;          // 0..71
                Ws[idx] = src[rk * 1024 + col];
            }
        }
        __syncthreads();

#pragma unroll 1
        for (int cil = 0; cil < 8; ++cil) {
#pragma unroll
            for (int ky = 0; ky < 3; ++ky) {
                const float* xp = &Xs[cil * 120 + (r + ky) * 12 + ccB];
                float4 xa = *(const float4*)xp;
                float4 xb = *(const float4*)(xp + 4);
                float xv[8] = {xa.x, xa.y, xa.z, xa.w, xb.x, xb.y, xb.z, xb.w};
#pragma unroll
                for (int kx = 0; kx < 3; ++kx) {
                    float4 wv = *(const float4*)&Ws[(cil * 9 + ky * 3 + kx) * 64 + tx * 4];
                    float wr[4] = {wv.x, wv.y, wv.z, wv.w};
#pragma unroll
                    for (int i = 0; i < 4; ++i)
#pragma unroll
                        for (int j = 0; j < 4; ++j)
                            acc[i][j] += wr[i] * xv[kx + j];
                }
            }
        }
    }

    // Epilogue: co<256 -> xo half of d_out; co>=256 -> qkv scratch
#pragma unroll
    for (int i = 0; i < 4; ++i) {
        int co = coBase + tx * 4 + i;
#pragma unroll
        for (int j = 0; j < 4; ++j) {
            int p = (py0 + r) * 32 + px0 + ccB + j;
            float v = acc[i][j];
            if (co < 256) {
                out[(b * 512 + co) * 1024 + p] = v + bconv[co];
            } else {
                g_qkv[(b * 768 + co - 256) * 1024 + p] = v + bqkv[co - 256];
            }
        }
    }
}

// ---------------------------------------------------------------------------
// Kernel 2: flash attention per (b, h). One warp per query row (8 rows/block).
// Key/value tiles of 128 staged in smem; lane owns 4 keys; O partials in regs.
// Output written in the reference's reshape layout: channel = h*32 + m/32,
// y = m%32, x = d.
// ---------------------------------------------------------------------------
__global__ __launch_bounds__(256) void attention_kernel(
    const float* __restrict__ krw,   // key_rel_w (63, 32)
    const float* __restrict__ krh) { // key_rel_h (63, 32)
    __shared__ float kt[32 * 128];
    __shared__ float vt[32 * 128];
    __shared__ float relw[8][64];
    __shared__ float relh[8][64];

    const int t = threadIdx.x;
    const int lane = t & 31;
    const int w = t >> 5;
    const int b = blockIdx.z;
    const int h = blockIdx.y;
    const int m = blockIdx.x * 8 + w;   // query index in [0, 1024)
    const int qx = m >> 5;              // H index
    const int qy = m & 31;              // W index

    // Load scaled q row into registers (broadcast across lanes)
    const float* qbase = &g_qkv[(b * 768 + h * 32) * 1024 + m];
    float q[32];
#pragma unroll
    for (int d = 0; d < 32; ++d) q[d] = qbase[d * 1024] * 0.17677669529663687f;

    // Precompute rel dot products: rwq[mm] = q . key_rel_w[mm], similarly rhq
    for (int mm = lane; mm < 63; mm += 32) {
        float sw = 0.f, sh = 0.f;
#pragma unroll
        for (int d = 0; d < 32; ++d) {
            sw += q[d] * krw[mm * 32 + d];
            sh += q[d] * krh[mm * 32 + d];
        }
        relw[w][mm] = sw;
        relh[w][mm] = sh;
    }
    __syncwarp();

    float o[32];
#pragma unroll
    for (int d = 0; d < 32; ++d) o[d] = 0.f;
    float M = -1e30f, L = 0.f;

    const float* kg = &g_qkv[(b * 768 + 256 + h * 32) * 1024];
    const float* vg = &g_qkv[(b * 768 + 512 + h * 32) * 1024];

    for (int tile = 0; tile < 8; ++tile) {
        __syncthreads();
#pragma unroll
        for (int i = 0; i < 16; ++i) {
            int idx = t + i * 256;           // 0..4095
            int d  = idx >> 7;
            int nl = idx & 127;
            kt[idx] = kg[d * 1024 + tile * 128 + nl];
            vt[idx] = vg[d * 1024 + tile * 128 + nl];
        }
        __syncthreads();

        // S phase: 4 keys per lane
        float s0 = 0.f, s1 = 0.f, s2 = 0.f, s3 = 0.f;
#pragma unroll
        for (int d = 0; d < 32; ++d) {
            float4 kv = *(const float4*)&kt[d * 128 + lane * 4];
            s0 += q[d] * kv.x; s1 += q[d] * kv.y;
            s2 += q[d] * kv.z; s3 += q[d] * kv.w;
        }
        // relative position terms: key n = tile*128 + lane*4 + j
        {
            int n0 = tile * 128 + lane * 4;
            int i0 = n0 >> 5;         // key row (all 4 keys share it: lane*4+3 < next multiple of 32)
            int j0 = n0 & 31;         // key col base
            float rh = relh[w][i0 - qx + 31];
            s0 += relw[w][j0     - qy + 31] + rh;
            s1 += relw[w][j0 + 1 - qy + 31] + rh;
            s2 += relw[w][j0 + 2 - qy + 31] + rh;
            s3 += relw[w][j0 + 3 - qy + 31] + rh;
        }
        // Online softmax update
        float mx = fmaxf(fmaxf(s0, s1), fmaxf(s2, s3));
#pragma unroll
        for (int off = 16; off; off >>= 1)
            mx = fmaxf(mx, __shfl_xor_sync(0xffffffffu, mx, off));
        float newM = fmaxf(M, mx);
        float scale = __expf(M - newM);
        M = newM;
        float e0 = __expf(s0 - newM), e1 = __expf(s1 - newM);
        float e2 = __expf(s2 - newM), e3 = __expf(s3 - newM);
        L = L * scale + (e0 + e1) + (e2 + e3);
        // O phase
#pragma unroll
        for (int d = 0; d < 32; ++d) {
            float4 vv = *(const float4*)&vt[d * 128 + lane * 4];
            o[d] = o[d] * scale + e0 * vv.x + e1 * vv.y + e2 * vv.z + e3 * vv.w;
        }
    }

    // Cross-lane reductions
#pragma unroll
    for (int off = 16; off; off >>= 1)
        L += __shfl_xor_sync(0xffffffffu, L, off);
    float of = 0.f;
#pragma unroll
    for (int d = 0; d < 32; ++d) {
        float v = o[d];
#pragma unroll
        for (int off = 16; off; off >>= 1)
            v += __shfl_xor_sync(0xffffffffu, v, off);
        if (lane == d) of = v;
    }
    // att.reshape(b, DV, H, W): channel = h*32 + qx, y = qy, x = d(=lane)
    g_att[((b * 256 + h * 32 + qx) * 32 + qy) * 32 + lane] = of / L;
}

// ---------------------------------------------------------------------------
// Kernel 3: 1x1 conv (GEMM M=256, N=1024, K=256 per batch) -> out[:, 256:512]
// ---------------------------------------------------------------------------
__global__ __launch_bounds__(256) void conv1x1_kernel(
    const float* __restrict__ batt,
    float* __restrict__ out) {
    __shared__ float Wk[16 * 64];
    __shared__ float Ak[16 * 64];
    const int t  = threadIdx.x;
    const int tx = t & 15;
    const int ty = t >> 4;
    const int b      = blockIdx.z;
    const int coBase = blockIdx.x * 64;
    const int pBase  = blockIdx.y * 64;

    float acc[4][4];
#pragma unroll
    for (int i = 0; i < 4; ++i)
#pragma unroll
        for (int j = 0; j < 4; ++j) acc[i][j] = 0.f;

    for (int ciB = 0; ciB < 256; ciB += 16) {
        __syncthreads();
#pragma unroll
        for (int i = 0; i < 4; ++i) {
            int idx = t + i * 256;
            int col = idx & 63;
            int cil = idx >> 6;
            Wk[idx] = g_watT[(ciB + cil) * 256 + coBase + col];
            Ak[idx] = g_att[(b * 256 + ciB + cil) * 1024 + pBase + col];
        }
        __syncthreads();
#pragma unroll
        for (int cil = 0; cil < 16; ++cil) {
            float4 wv = *(const float4*)&Wk[cil * 64 + tx * 4];
            float4 av = *(const float4*)&Ak[cil * 64 + ty * 4];
            float wr[4] = {wv.x, wv.y, wv.z, wv.w};
            float ar[4] = {av.x, av.y, av.z, av.w};
#pragma unroll
            for (int i = 0; i < 4; ++i)
#pragma unroll
                for (int j = 0; j < 4; ++j)
                    acc[i][j] += wr[i] * ar[j];
        }
    }

#pragma unroll
    for (int i = 0; i < 4; ++i) {
        int co = coBase + tx * 4 + i;
        float bb = batt[co];
#pragma unroll
        for (int j = 0; j < 4; ++j) {
            int p = pBase + ty * 4 + j;
            out[(b * 512 + 256 + co) * 1024 + p] = acc[i][j] + bb;
        }
    }
}

// ---------------------------------------------------------------------------
// Launch
// ---------------------------------------------------------------------------
extern "C" void kernel_launch(void* const* d_in, const int* in_sizes, int n_in,
                              void* d_out, int out_size) {
    const float* x      = (const float*)d_in[0];
    const float* w_conv = (const float*)d_in[1];
    const float* b_conv = (const float*)d_in[2];
    const float* w_qkv  = (const float*)d_in[3];
    const float* b_qkv  = (const float*)d_in[4];
    const float* w_att  = (const float*)d_in[5];
    const float* b_att  = (const float*)d_in[6];
    const float* krw    = (const float*)d_in[7];
    const float* krh    = (const float*)d_in[8];
    float* out = (float*)d_out;

    prep_weights<<<(2304 * 1024 + 255) / 256, 256>>>(w_conv, w_qkv, w_att);
    conv3x3_kernel<<<dim3(16, 16, 8), 256>>>(x, b_conv, b_qkv, out);
    attention_kernel<<<dim3(128, 8, 8), 256>>>(krw, krh);
    conv1x1_kernel<<<dim3(4, 16, 8), 256>>>(b_att, out);
}